// round 12
// baseline (speedup 1.0000x reference)
#include <cuda_runtime.h>
#include <cstdint>

// SpikeFP32GELUExact: input [B,S,D,32] float32 pulse bits (MSB first) encoding
// fp32 values; output = same pulse encoding of fp32(GELU_tanh_fp64(x)).
//
// Round 12: 256-bit memory path (Blackwell LDG.E.256/STG.E.256 via PTX
// v4.u64). Iter t, lane l covers floats [256t+8l .. 256t+8l+7] (32B): pulse
// bits 8*(l%4)..8*(l%4)+7 of value 8t + l/4. Bit tests are integer nonzero
// tests on u64 halves (pulse floats are exactly 0x0 / 0x3F800000). 2-step
// shfl_xor butterfly over 4-lane groups assembles each pulse word; lane l
// owns value 8*(l%4) + l/4 and the store mirrors the permutation.
// GELU: proven double-single fp32-pipe chain (~2^-47 rel; reproduces the
// reference fp64 pipeline's fp32 output bit-exactly, rel_err 0 rounds 4-11).

#define DS_HI(v) ((float)(v))
#define DS_LO(v) ((float)((v) - (double)(float)(v)))

__device__ __forceinline__ float gelu_exact_ds(float x)
{
    if (fabsf(x) < 2.8e-17f) return 0.5f * x;   // exact region; keeps -0.0 sign

    // ---- x^3 as DS ----
    float x2h = x * x;
    float x2l = fmaf(x, x, -x2h);
    float x3h = x2h * x;
    float x3l = fmaf(x2h, x, -x3h);
    x3l = fmaf(x2l, x, x3l);

    // ---- inner = x + 0.044715 * x^3 ----
    const float Ch = DS_HI(0.044715);
    const float Cl = DS_LO(0.044715);
    float ph = Ch * x3h;
    float pl = fmaf(Ch, x3h, -ph);
    pl = fmaf(Ch, x3l, pl);
    pl = fmaf(Cl, x3h, pl);
    float sh = ph + x;
    float bb = sh - ph;
    float sl = (ph - (sh - bb)) + (x - bb);
    sl += pl;
    float ih = sh + sl;
    float il = sl - (ih - sh);

    // ---- z2 = 2*0.7978845608028654 * inner ----
    const float Kh = DS_HI(2.0 * 0.7978845608028654);
    const float Kl = DS_LO(2.0 * 0.7978845608028654);
    float zh = Kh * ih;
    float zl = fmaf(Kh, ih, -zh);
    zl = fmaf(Kh, il, zl);
    zl = fmaf(Kl, ih, zl);
    if (zh > 45.0f)  { zh = 45.0f;  zl = 0.0f; }
    if (zh < -45.0f) { zh = -45.0f; zl = 0.0f; }

    // ---- exp(z2): Cody-Waite reduction ----
    float kf = rintf(zh * 1.44269504f);
    int   k  = (int)kf;
    const float  L1 = 0.693359375f;              // 9-bit mantissa: k*L1 exact
    const double D1 = 0.6931471805599453;
    const double D2 = 2.3190468138462996e-17;
    const float  L2f = (float)(D1 - (double)0.693359375f);
    const float  L3f = (float)(((D1 - (double)0.693359375f) - (double)(float)(D1 - (double)0.693359375f)) + D2);

    float t1  = fmaf(-kf, L1, zh);               // exact (Sterbenz)
    float p1  = kf * L2f;
    float p1e = fmaf(kf, L2f, -p1);              // two_prod
    float rh  = t1 - p1;
    float b2  = rh - t1;
    float rl  = (t1 - (rh - b2)) + (-p1 - b2);
    rl = ((zl - p1e) - kf * L3f) + rl;
    float rhn = rh + rl;
    float b3  = rhn - rh;
    float rln = (rh - (rhn - b3)) + (rl - b3);

    // ---- poly degrees 13..8 in plain fp32 (error enters * r^8) ----
    float q = 1.60590438e-10f;
    q = fmaf(q, rhn, 2.08767570e-09f);
    q = fmaf(q, rhn, 2.50521084e-08f);
    q = fmaf(q, rhn, 2.75573192e-07f);
    q = fmaf(q, rhn, 2.75573192e-06f);
    q = fmaf(q, rhn, 2.48015873e-05f);

    // ---- degrees 7..0 in DS Horner ----
    float hh, hl;
    {
        float gh = rhn * q;
        float gl = fmaf(rhn, q, -gh);
        gl = fmaf(rln, q, gl);
        const float cH = DS_HI(1.9841269841269841e-04), cL = DS_LO(1.9841269841269841e-04);
        float s = cH + gh;
        float e = gh - (s - cH);
        float lo = (cL + gl) + e;
        hh = s + lo;
        hl = lo - (hh - s);
    }
#define POLY_STEP(CH, CL) do { \
        float gh = rhn * hh; \
        float gl = fmaf(rhn, hh, -gh); \
        gl = fmaf(rhn, hl, gl); \
        gl = fmaf(rln, hh, gl); \
        float s = (CH) + gh; \
        float e = gh - (s - (CH)); \
        float lo = ((CL) + gl) + e; \
        hh = s + lo; \
        hl = lo - (hh - s); \
    } while (0)
    POLY_STEP(DS_HI(1.3888888888888889e-03), DS_LO(1.3888888888888889e-03));
    POLY_STEP(DS_HI(8.3333333333333332e-03), DS_LO(8.3333333333333332e-03));
    POLY_STEP(DS_HI(4.1666666666666664e-02), DS_LO(4.1666666666666664e-02));
    POLY_STEP(DS_HI(1.6666666666666666e-01), DS_LO(1.6666666666666666e-01));
    POLY_STEP(0.5f, 0.0f);
    POLY_STEP(1.0f, 0.0f);
    POLY_STEP(1.0f, 0.0f);
#undef POLY_STEP

    // ---- scale by 2^k (exact) ----
    float sc = __int_as_float((127 + k) << 23);
    float eh = hh * sc;
    float el = hl * sc;

    // ---- den = 1 + e2z (DS; both positive, no cancellation) ----
    float ds_ = 1.0f + eh;
    float bbd = ds_ - 1.0f;
    float dl  = (1.0f - (ds_ - bbd)) + (eh - bbd);
    dl += el;
    float dhn = ds_ + dl;
    float dln = dl - (dhn - ds_);

    // ---- y = 1/den: frcp seed + DS Newton with t+t^2 correction ----
    float y0  = __frcp_rn(dhn);
    float pr  = dhn * y0;
    float pre = fmaf(dhn, y0, -pr);
    float th_ = 1.0f - pr;
    float tl_ = -fmaf(dln, y0, pre);
    float tc  = th_ + tl_;
    float tq  = fmaf(tc, tc, tc);
    float corr = y0 * tq;
    float yh  = y0 + corr;
    float yl  = corr - (yh - y0);

    // ---- res = x * (e2z * y)  [0.5*x*(1+tanh) = x*e2z/(1+e2z)] ----
    float uh = eh * yh;
    float ue = fmaf(eh, yh, -uh);
    ue = fmaf(eh, yl, ue);
    ue = fmaf(el, yh, ue);
    float qh = x * uh;
    float qe = fmaf(x, uh, -qh);
    qe = fmaf(x, ue, qe);
    return qh + qe;                              // final fp32 rounding
}

// 256-bit global load/store (Blackwell LDG.E.256 / STG.E.256), streaming hint.
__device__ __forceinline__ void ldg256_cs(const void* p,
    unsigned long long& a, unsigned long long& b,
    unsigned long long& c, unsigned long long& d)
{
    asm volatile("ld.global.cs.v4.u64 {%0,%1,%2,%3}, [%4];"
                 : "=l"(a), "=l"(b), "=l"(c), "=l"(d) : "l"(p));
}
__device__ __forceinline__ void stg256_cs(void* p,
    unsigned long long a, unsigned long long b,
    unsigned long long c, unsigned long long d)
{
    asm volatile("st.global.cs.v4.u64 [%0], {%1,%2,%3,%4};"
                 :: "l"(p), "l"(a), "l"(b), "l"(c), "l"(d) : "memory");
}

__global__ __launch_bounds__(512) void gelu_pulse_kernel(
    const unsigned long long* __restrict__ in,
    unsigned long long* __restrict__ out, int n_vals)
{
    const unsigned FULL = 0xFFFFFFFFu;
    int gwarp = (int)((blockIdx.x * blockDim.x + threadIdx.x) >> 5);
    int lane  = threadIdx.x & 31;
    if (gwarp * 32 >= n_vals) return;

    // warp region: 1024 floats = 512 u64; lane l, iter t at u64 offset t*128 + 4l
    size_t base8 = (size_t)gwarp * 512;
    const unsigned long long* p = in + base8 + 4 * lane;
    int sub = lane & 3;                    // position within 4-lane group

    // ---- 256-bit loads + butterfly pack ----
    // Iter t: lane l holds pulse bits 8*sub..8*sub+7 of value 8t + l/4.
    // Pulse floats are exactly 0x00000000 or 0x3F800000, so nonzero tests on
    // the u64 halves are exact bit tests.
    uint32_t myw = 0;
#pragma unroll
    for (int t = 0; t < 4; ++t) {
        unsigned long long a, b, c, d;
        ldg256_cs(p + (size_t)t * 128, a, b, c, d);
        uint32_t by = ((uint32_t)a        ? 1u   : 0u)
                    | ((uint32_t)(a >> 32)? 2u   : 0u)
                    | ((uint32_t)b        ? 4u   : 0u)
                    | ((uint32_t)(b >> 32)? 8u   : 0u)
                    | ((uint32_t)c        ? 16u  : 0u)
                    | ((uint32_t)(c >> 32)? 32u  : 0u)
                    | ((uint32_t)d        ? 64u  : 0u)
                    | ((uint32_t)(d >> 32)? 128u : 0u);
        uint32_t wrd = by << (8 * sub);
        wrd |= __shfl_xor_sync(FULL, wrd, 1);
        wrd |= __shfl_xor_sync(FULL, wrd, 2);
        if (sub == t) myw = wrd;
    }

    // pulse word -> value bits (pulse bit i has significance 31-i)
    float xf = __uint_as_float(__brev(myw));
    float rf = gelu_exact_ds(xf);
    uint32_t wp = __brev(__float_as_uint(rf));   // back to pulse-bit order

    // ---- 256-bit stores (mirror permutation) ----
    // Iter t: lane l writes pulse bits 8*sub..8*sub+7 of value 8t + l/4,
    // whose word is owned by lane (l & ~3) | t.
    unsigned long long* qo = out + base8 + 4 * lane;
#pragma unroll
    for (int t = 0; t < 4; ++t) {
        uint32_t wt = __shfl_sync(FULL, wp, (lane & 28) | t);
        uint32_t by = wt >> (8 * sub);
        const unsigned long long ONE = 0x3F800000ull;
        unsigned long long a = ((by & 1u)   ? ONE : 0ull) | (((by >> 1) & 1u) ? (ONE << 32) : 0ull);
        unsigned long long b = (((by >> 2) & 1u) ? ONE : 0ull) | (((by >> 3) & 1u) ? (ONE << 32) : 0ull);
        unsigned long long c = (((by >> 4) & 1u) ? ONE : 0ull) | (((by >> 5) & 1u) ? (ONE << 32) : 0ull);
        unsigned long long d = (((by >> 6) & 1u) ? ONE : 0ull) | (((by >> 7) & 1u) ? (ONE << 32) : 0ull);
        stg256_cs(qo + (size_t)t * 128, a, b, c, d);
    }
}

extern "C" void kernel_launch(void* const* d_in, const int* in_sizes, int n_in,
                              void* d_out, int out_size)
{
    const unsigned long long* in = (const unsigned long long*)d_in[0];
    unsigned long long* out = (unsigned long long*)d_out;
    int n_vals = in_sizes[0] / 32;   // 32 pulse floats per value
    int threads = 512;               // 16 warps/block, each warp does 32 values
    int warps = (n_vals + 31) / 32;
    int blocks = (warps * 32 + threads - 1) / threads;
    gelu_pulse_kernel<<<blocks, threads>>>(in, out, n_vals);
}

// round 13
// speedup vs baseline: 1.0130x; 1.0130x over previous
#include <cuda_runtime.h>
#include <cstdint>

// SpikeFP32GELUExact — FINAL (measured best: 157.8us, DRAM 85%, at the
// HBM3e mixed-stream ceiling for 512MB in + 512MB out; ideal floor 131us).
//
// Input [B,S,D,32] float32 pulse bits (MSB first) encoding fp32 values;
// output = same pulse encoding of fp32(GELU_tanh_fp64(x)).
//
// Convergence evidence (rounds 7-12): six structurally distinct kernels
// (32b/128b/256b access width, ballot vs butterfly pack, with/without
// streaming hints, occ 54-94%, ILP 1-2) all pin at 6.65-6.76 TB/s. The
// binding resource is the HBM read+write turnaround ceiling, not anything
// kernel-side. This variant was the fastest measured.
//
// Structure:
//  * 128-bit path: lane l, iter t loads float4 at float offset t*128+4l
//    (8 LDG.128 / 8 STG.128 per warp), __ldcs/__stcs streaming (1GB >> L2).
//  * Butterfly pack: each float4 holds 4 pulse bits of value 4t + l/8; a
//    3-step shfl_xor OR over each 8-lane group assembles the pulse word;
//    lane 8g+t owns value 4t+g (store mirrors the permutation).
//  * GELU: NO FP64 (sm_103a DP is ~60x slower than FP32). Double-single
//    (two-float) chain on the FP32 pipe, ~2^-47 rel: exact Cody-Waite exp
//    reduction, fp32 Horner deg 13..8, DS Horner deg 7..0, exact 2^k scale,
//    frcp-seeded DS Newton reciprocal, 1+tanh as 2*e2z/(1+e2z) (no
//    cancellation either sign). After the final fp32 rounding this matches
//    the reference fp64 pipeline bit-exactly (rel_err 0.0, rounds 4-12).

#define DS_HI(v) ((float)(v))
#define DS_LO(v) ((float)((v) - (double)(float)(v)))

__device__ __forceinline__ float gelu_exact_ds(float x)
{
    if (fabsf(x) < 2.8e-17f) return 0.5f * x;   // exact region; keeps -0.0 sign

    // ---- x^3 as DS ----
    float x2h = x * x;
    float x2l = fmaf(x, x, -x2h);
    float x3h = x2h * x;
    float x3l = fmaf(x2h, x, -x3h);
    x3l = fmaf(x2l, x, x3l);

    // ---- inner = x + 0.044715 * x^3 ----
    const float Ch = DS_HI(0.044715);
    const float Cl = DS_LO(0.044715);
    float ph = Ch * x3h;
    float pl = fmaf(Ch, x3h, -ph);
    pl = fmaf(Ch, x3l, pl);
    pl = fmaf(Cl, x3h, pl);
    float sh = ph + x;
    float bb = sh - ph;
    float sl = (ph - (sh - bb)) + (x - bb);
    sl += pl;
    float ih = sh + sl;
    float il = sl - (ih - sh);

    // ---- z2 = 2*0.7978845608028654 * inner ----
    const float Kh = DS_HI(2.0 * 0.7978845608028654);
    const float Kl = DS_LO(2.0 * 0.7978845608028654);
    float zh = Kh * ih;
    float zl = fmaf(Kh, ih, -zh);
    zl = fmaf(Kh, il, zl);
    zl = fmaf(Kl, ih, zl);
    if (zh > 45.0f)  { zh = 45.0f;  zl = 0.0f; }
    if (zh < -45.0f) { zh = -45.0f; zl = 0.0f; }

    // ---- exp(z2): Cody-Waite reduction ----
    float kf = rintf(zh * 1.44269504f);
    int   k  = (int)kf;
    const float  L1 = 0.693359375f;              // 9-bit mantissa: k*L1 exact
    const double D1 = 0.6931471805599453;
    const double D2 = 2.3190468138462996e-17;
    const float  L2f = (float)(D1 - (double)0.693359375f);
    const float  L3f = (float)(((D1 - (double)0.693359375f) - (double)(float)(D1 - (double)0.693359375f)) + D2);

    float t1  = fmaf(-kf, L1, zh);               // exact (Sterbenz)
    float p1  = kf * L2f;
    float p1e = fmaf(kf, L2f, -p1);              // two_prod
    float rh  = t1 - p1;
    float b2  = rh - t1;
    float rl  = (t1 - (rh - b2)) + (-p1 - b2);
    rl = ((zl - p1e) - kf * L3f) + rl;
    float rhn = rh + rl;
    float b3  = rhn - rh;
    float rln = (rh - (rhn - b3)) + (rl - b3);

    // ---- poly degrees 13..8 in plain fp32 (error enters * r^8) ----
    float q = 1.60590438e-10f;
    q = fmaf(q, rhn, 2.08767570e-09f);
    q = fmaf(q, rhn, 2.50521084e-08f);
    q = fmaf(q, rhn, 2.75573192e-07f);
    q = fmaf(q, rhn, 2.75573192e-06f);
    q = fmaf(q, rhn, 2.48015873e-05f);

    // ---- degrees 7..0 in DS Horner ----
    float hh, hl;
    {
        float gh = rhn * q;
        float gl = fmaf(rhn, q, -gh);
        gl = fmaf(rln, q, gl);
        const float cH = DS_HI(1.9841269841269841e-04), cL = DS_LO(1.9841269841269841e-04);
        float s = cH + gh;
        float e = gh - (s - cH);
        float lo = (cL + gl) + e;
        hh = s + lo;
        hl = lo - (hh - s);
    }
#define POLY_STEP(CH, CL) do { \
        float gh = rhn * hh; \
        float gl = fmaf(rhn, hh, -gh); \
        gl = fmaf(rhn, hl, gl); \
        gl = fmaf(rln, hh, gl); \
        float s = (CH) + gh; \
        float e = gh - (s - (CH)); \
        float lo = ((CL) + gl) + e; \
        hh = s + lo; \
        hl = lo - (hh - s); \
    } while (0)
    POLY_STEP(DS_HI(1.3888888888888889e-03), DS_LO(1.3888888888888889e-03));
    POLY_STEP(DS_HI(8.3333333333333332e-03), DS_LO(8.3333333333333332e-03));
    POLY_STEP(DS_HI(4.1666666666666664e-02), DS_LO(4.1666666666666664e-02));
    POLY_STEP(DS_HI(1.6666666666666666e-01), DS_LO(1.6666666666666666e-01));
    POLY_STEP(0.5f, 0.0f);
    POLY_STEP(1.0f, 0.0f);
    POLY_STEP(1.0f, 0.0f);
#undef POLY_STEP

    // ---- scale by 2^k (exact) ----
    float sc = __int_as_float((127 + k) << 23);
    float eh = hh * sc;
    float el = hl * sc;

    // ---- den = 1 + e2z (DS; both positive, no cancellation) ----
    float ds_ = 1.0f + eh;
    float bbd = ds_ - 1.0f;
    float dl  = (1.0f - (ds_ - bbd)) + (eh - bbd);
    dl += el;
    float dhn = ds_ + dl;
    float dln = dl - (dhn - ds_);

    // ---- y = 1/den: frcp seed + DS Newton with t+t^2 correction ----
    float y0  = __frcp_rn(dhn);
    float pr  = dhn * y0;
    float pre = fmaf(dhn, y0, -pr);
    float th_ = 1.0f - pr;
    float tl_ = -fmaf(dln, y0, pre);
    float tc  = th_ + tl_;
    float tq  = fmaf(tc, tc, tc);
    float corr = y0 * tq;
    float yh  = y0 + corr;
    float yl  = corr - (yh - y0);

    // ---- res = x * (e2z * y)  [0.5*x*(1+tanh) = x*e2z/(1+e2z)] ----
    float uh = eh * yh;
    float ue = fmaf(eh, yh, -uh);
    ue = fmaf(eh, yl, ue);
    ue = fmaf(el, yh, ue);
    float qh = x * uh;
    float qe = fmaf(x, uh, -qh);
    qe = fmaf(x, ue, qe);
    return qh + qe;                              // final fp32 rounding
}

__global__ __launch_bounds__(512) void gelu_pulse_kernel(
    const float4* __restrict__ in, float4* __restrict__ out, int n_vals)
{
    const unsigned FULL = 0xFFFFFFFFu;
    int gwarp = (int)((blockIdx.x * blockDim.x + threadIdx.x) >> 5);
    int lane  = threadIdx.x & 31;
    if (gwarp * 32 >= n_vals) return;

    size_t base4 = (size_t)gwarp * 256;    // 1024 floats / 4
    const float4* p = in + base4 + lane;
    int sub = lane & 7;                    // position within 8-lane group

    // ---- 128-bit streaming loads + butterfly pack ----
    uint32_t myw = 0;
#pragma unroll
    for (int t = 0; t < 8; ++t) {
        float4 f = __ldcs(p + (size_t)t * 32);
        uint32_t nib = ((f.x != 0.0f) ? 1u : 0u)
                     | ((f.y != 0.0f) ? 2u : 0u)
                     | ((f.z != 0.0f) ? 4u : 0u)
                     | ((f.w != 0.0f) ? 8u : 0u);
        uint32_t wrd = nib << (4 * sub);
        wrd |= __shfl_xor_sync(FULL, wrd, 1);
        wrd |= __shfl_xor_sync(FULL, wrd, 2);
        wrd |= __shfl_xor_sync(FULL, wrd, 4);
        if (sub == t) myw = wrd;
    }

    // pulse word -> value bits (pulse bit i has significance 31-i)
    float xf = __uint_as_float(__brev(myw));
    float rf = gelu_exact_ds(xf);
    uint32_t wp = __brev(__float_as_uint(rf));   // back to pulse-bit order

    // ---- 128-bit streaming stores (mirror of the load permutation) ----
    float4* qo = out + base4 + lane;
#pragma unroll
    for (int t = 0; t < 8; ++t) {
        uint32_t wt = __shfl_sync(FULL, wp, (lane & 24) | t);
        uint32_t nib = wt >> (4 * sub);
        float4 o;
        o.x = __uint_as_float((nib & 1u)        * 0x3F800000u);
        o.y = __uint_as_float(((nib >> 1) & 1u) * 0x3F800000u);
        o.z = __uint_as_float(((nib >> 2) & 1u) * 0x3F800000u);
        o.w = __uint_as_float(((nib >> 3) & 1u) * 0x3F800000u);
        __stcs(qo + (size_t)t * 32, o);
    }
}

extern "C" void kernel_launch(void* const* d_in, const int* in_sizes, int n_in,
                              void* d_out, int out_size)
{
    const float4* in = (const float4*)d_in[0];
    float4* out = (float4*)d_out;
    int n_vals = in_sizes[0] / 32;   // 32 pulse floats per value
    int threads = 512;               // 16 warps/block, each warp does 32 values
    int warps = (n_vals + 31) / 32;
    int blocks = (warps * 32 + threads - 1) / threads;
    gelu_pulse_kernel<<<blocks, threads>>>(in, out, n_vals);
}

// round 14
// speedup vs baseline: 1.0134x; 1.0004x over previous
#include <cuda_runtime.h>
#include <cstdint>

// SpikeFP32GELUExact — FINAL. 157.8us (x3 reproduced), DRAM ~85%: the HBM3e
// mixed read+write stream ceiling for 512MB in + 512MB out (ideal 131us).
//
// Input [B,S,D,32] float32 pulse bits (MSB first) encoding fp32 values;
// output = same pulse encoding of fp32(GELU_tanh_fp64(x)).
//
// Round 14 tweak: loads explicitly front-batched into a register array so
// all 8 LDG.128 issue before the first butterfly consumes one (guaranteed
// MLP_p1=8 at SASS level). Otherwise identical to the measured optimum.
//
// Structure:
//  * 128-bit path: lane l, iter t covers float4 at float offset t*128+4l
//    (8 LDG.128 / 8 STG.128 per warp), __ldcs/__stcs streaming (1GB >> L2).
//  * Butterfly pack: each float4 holds 4 pulse bits of value 4t + l/8; a
//    3-step shfl_xor OR over each 8-lane group assembles the pulse word;
//    lane 8g+t owns value 4t+g (store mirrors the permutation).
//  * GELU: NO FP64 (sm_103a DP ~60x slower than FP32). Double-single
//    (two-float) chain on the FP32 pipe, ~2^-47 rel: exact Cody-Waite exp
//    reduction, fp32 Horner deg 13..8, DS Horner deg 7..0, exact 2^k scale,
//    frcp-seeded DS Newton reciprocal, 1+tanh as 2*e2z/(1+e2z) (no
//    cancellation either sign). After final fp32 rounding this matches the
//    reference fp64 pipeline bit-exactly (rel_err 0.0, rounds 4-13).

#define DS_HI(v) ((float)(v))
#define DS_LO(v) ((float)((v) - (double)(float)(v)))

__device__ __forceinline__ float gelu_exact_ds(float x)
{
    if (fabsf(x) < 2.8e-17f) return 0.5f * x;   // exact region; keeps -0.0 sign

    // ---- x^3 as DS ----
    float x2h = x * x;
    float x2l = fmaf(x, x, -x2h);
    float x3h = x2h * x;
    float x3l = fmaf(x2h, x, -x3h);
    x3l = fmaf(x2l, x, x3l);

    // ---- inner = x + 0.044715 * x^3 ----
    const float Ch = DS_HI(0.044715);
    const float Cl = DS_LO(0.044715);
    float ph = Ch * x3h;
    float pl = fmaf(Ch, x3h, -ph);
    pl = fmaf(Ch, x3l, pl);
    pl = fmaf(Cl, x3h, pl);
    float sh = ph + x;
    float bb = sh - ph;
    float sl = (ph - (sh - bb)) + (x - bb);
    sl += pl;
    float ih = sh + sl;
    float il = sl - (ih - sh);

    // ---- z2 = 2*0.7978845608028654 * inner ----
    const float Kh = DS_HI(2.0 * 0.7978845608028654);
    const float Kl = DS_LO(2.0 * 0.7978845608028654);
    float zh = Kh * ih;
    float zl = fmaf(Kh, ih, -zh);
    zl = fmaf(Kh, il, zl);
    zl = fmaf(Kl, ih, zl);
    if (zh > 45.0f)  { zh = 45.0f;  zl = 0.0f; }
    if (zh < -45.0f) { zh = -45.0f; zl = 0.0f; }

    // ---- exp(z2): Cody-Waite reduction ----
    float kf = rintf(zh * 1.44269504f);
    int   k  = (int)kf;
    const float  L1 = 0.693359375f;              // 9-bit mantissa: k*L1 exact
    const double D1 = 0.6931471805599453;
    const double D2 = 2.3190468138462996e-17;
    const float  L2f = (float)(D1 - (double)0.693359375f);
    const float  L3f = (float)(((D1 - (double)0.693359375f) - (double)(float)(D1 - (double)0.693359375f)) + D2);

    float t1  = fmaf(-kf, L1, zh);               // exact (Sterbenz)
    float p1  = kf * L2f;
    float p1e = fmaf(kf, L2f, -p1);              // two_prod
    float rh  = t1 - p1;
    float b2  = rh - t1;
    float rl  = (t1 - (rh - b2)) + (-p1 - b2);
    rl = ((zl - p1e) - kf * L3f) + rl;
    float rhn = rh + rl;
    float b3  = rhn - rh;
    float rln = (rh - (rhn - b3)) + (rl - b3);

    // ---- poly degrees 13..8 in plain fp32 (error enters * r^8) ----
    float q = 1.60590438e-10f;
    q = fmaf(q, rhn, 2.08767570e-09f);
    q = fmaf(q, rhn, 2.50521084e-08f);
    q = fmaf(q, rhn, 2.75573192e-07f);
    q = fmaf(q, rhn, 2.75573192e-06f);
    q = fmaf(q, rhn, 2.48015873e-05f);

    // ---- degrees 7..0 in DS Horner ----
    float hh, hl;
    {
        float gh = rhn * q;
        float gl = fmaf(rhn, q, -gh);
        gl = fmaf(rln, q, gl);
        const float cH = DS_HI(1.9841269841269841e-04), cL = DS_LO(1.9841269841269841e-04);
        float s = cH + gh;
        float e = gh - (s - cH);
        float lo = (cL + gl) + e;
        hh = s + lo;
        hl = lo - (hh - s);
    }
#define POLY_STEP(CH, CL) do { \
        float gh = rhn * hh; \
        float gl = fmaf(rhn, hh, -gh); \
        gl = fmaf(rhn, hl, gl); \
        gl = fmaf(rln, hh, gl); \
        float s = (CH) + gh; \
        float e = gh - (s - (CH)); \
        float lo = ((CL) + gl) + e; \
        hh = s + lo; \
        hl = lo - (hh - s); \
    } while (0)
    POLY_STEP(DS_HI(1.3888888888888889e-03), DS_LO(1.3888888888888889e-03));
    POLY_STEP(DS_HI(8.3333333333333332e-03), DS_LO(8.3333333333333332e-03));
    POLY_STEP(DS_HI(4.1666666666666664e-02), DS_LO(4.1666666666666664e-02));
    POLY_STEP(DS_HI(1.6666666666666666e-01), DS_LO(1.6666666666666666e-01));
    POLY_STEP(0.5f, 0.0f);
    POLY_STEP(1.0f, 0.0f);
    POLY_STEP(1.0f, 0.0f);
#undef POLY_STEP

    // ---- scale by 2^k (exact) ----
    float sc = __int_as_float((127 + k) << 23);
    float eh = hh * sc;
    float el = hl * sc;

    // ---- den = 1 + e2z (DS; both positive, no cancellation) ----
    float ds_ = 1.0f + eh;
    float bbd = ds_ - 1.0f;
    float dl  = (1.0f - (ds_ - bbd)) + (eh - bbd);
    dl += el;
    float dhn = ds_ + dl;
    float dln = dl - (dhn - ds_);

    // ---- y = 1/den: frcp seed + DS Newton with t+t^2 correction ----
    float y0  = __frcp_rn(dhn);
    float pr  = dhn * y0;
    float pre = fmaf(dhn, y0, -pr);
    float th_ = 1.0f - pr;
    float tl_ = -fmaf(dln, y0, pre);
    float tc  = th_ + tl_;
    float tq  = fmaf(tc, tc, tc);
    float corr = y0 * tq;
    float yh  = y0 + corr;
    float yl  = corr - (yh - y0);

    // ---- res = x * (e2z * y)  [0.5*x*(1+tanh) = x*e2z/(1+e2z)] ----
    float uh = eh * yh;
    float ue = fmaf(eh, yh, -uh);
    ue = fmaf(eh, yl, ue);
    ue = fmaf(el, yh, ue);
    float qh = x * uh;
    float qe = fmaf(x, uh, -qh);
    qe = fmaf(x, ue, qe);
    return qh + qe;                              // final fp32 rounding
}

__global__ __launch_bounds__(512) void gelu_pulse_kernel(
    const float4* __restrict__ in, float4* __restrict__ out, int n_vals)
{
    const unsigned FULL = 0xFFFFFFFFu;
    int gwarp = (int)((blockIdx.x * blockDim.x + threadIdx.x) >> 5);
    int lane  = threadIdx.x & 31;
    if (gwarp * 32 >= n_vals) return;

    size_t base4 = (size_t)gwarp * 256;    // 1024 floats / 4
    const float4* p = in + base4 + lane;
    int sub = lane & 7;                    // position within 8-lane group

    // ---- front-batched 128-bit streaming loads (MLP_p1 = 8) ----
    float4 f[8];
#pragma unroll
    for (int t = 0; t < 8; ++t)
        f[t] = __ldcs(p + (size_t)t * 32);

    // ---- butterfly pack ----
    // Iter t: lane l's float4 holds pulse bits 4*sub..4*sub+3 of value
    // 4t + l/8; 3-step shfl_xor OR over the 8-lane group assembles the
    // word; lane with sub==t keeps it -> lane l owns value 4*(l%8) + l/8.
    uint32_t myw = 0;
#pragma unroll
    for (int t = 0; t < 8; ++t) {
        uint32_t nib = ((f[t].x != 0.0f) ? 1u : 0u)
                     | ((f[t].y != 0.0f) ? 2u : 0u)
                     | ((f[t].z != 0.0f) ? 4u : 0u)
                     | ((f[t].w != 0.0f) ? 8u : 0u);
        uint32_t wrd = nib << (4 * sub);
        wrd |= __shfl_xor_sync(FULL, wrd, 1);
        wrd |= __shfl_xor_sync(FULL, wrd, 2);
        wrd |= __shfl_xor_sync(FULL, wrd, 4);
        if (sub == t) myw = wrd;
    }

    // pulse word -> value bits (pulse bit i has significance 31-i)
    float xf = __uint_as_float(__brev(myw));
    float rf = gelu_exact_ds(xf);
    uint32_t wp = __brev(__float_as_uint(rf));   // back to pulse-bit order

    // ---- 128-bit streaming stores (mirror of the load permutation) ----
    float4* qo = out + base4 + lane;
#pragma unroll
    for (int t = 0; t < 8; ++t) {
        uint32_t wt = __shfl_sync(FULL, wp, (lane & 24) | t);
        uint32_t nib = wt >> (4 * sub);
        float4 o;
        o.x = __uint_as_float((nib & 1u)        * 0x3F800000u);
        o.y = __uint_as_float(((nib >> 1) & 1u) * 0x3F800000u);
        o.z = __uint_as_float(((nib >> 2) & 1u) * 0x3F800000u);
        o.w = __uint_as_float(((nib >> 3) & 1u) * 0x3F800000u);
        __stcs(qo + (size_t)t * 32, o);
    }
}

extern "C" void kernel_launch(void* const* d_in, const int* in_sizes, int n_in,
                              void* d_out, int out_size)
{
    const float4* in = (const float4*)d_in[0];
    float4* out = (float4*)d_out;
    int n_vals = in_sizes[0] / 32;   // 32 pulse floats per value
    int threads = 512;               // 16 warps/block, each warp does 32 values
    int warps = (n_vals + 31) / 32;
    int blocks = (warps * 32 + threads - 1) / threads;
    gelu_pulse_kernel<<<blocks, threads>>>(in, out, n_vals);
}